// round 7
// baseline (speedup 1.0000x reference)
#include <cuda_runtime.h>
#include <cuda_fp16.h>
#include <cuda_bf16.h>
#include <math.h>

#define NN 100000
#define EE 1600000
#define NEG_SLOPE 0.2f
#define SCAN_B 512
#define NBLK ((NN + SCAN_B - 1) / SCAN_B)   // 196

// ---------------- scratch (device globals) ----------------
__device__ float g_h1[NN * 64];     // layer1 GEMM output [N,H*D] (fp32)
__device__ float g_as1[NN * 8];     // per-node/head src logit
__device__ float g_ad1[NN * 8];     // per-node/head dst logit
__device__ float g_g2[NN * 16];     // layer2 GEMM output
__device__ float g_as2[NN];
__device__ float g_ad2[NN];
__device__ int   g_deg[NN];         // zero at load; self-reset by s3 each call
__device__ int   g_off[NN + 1];     // CSR offsets with sentinel off[NN]=EE
__device__ int   g_pos[NN];
__device__ int   g_csr[EE];         // src node ids, grouped by dst
__device__ int   g_bsum[NBLK];

// ---------------- CSR build ----------------
__global__ void k_hist(const int* __restrict__ dst) {
    int e = blockIdx.x * blockDim.x + threadIdx.x;
    if (e < EE) atomicAdd(&g_deg[dst[e]], 1);
}

__global__ void s1_scan() {
    __shared__ int sd[SCAN_B];
    int i = blockIdx.x * SCAN_B + threadIdx.x;
    int v = (i < NN) ? g_deg[i] : 0;
    sd[threadIdx.x] = v;
    __syncthreads();
    for (int ofs = 1; ofs < SCAN_B; ofs <<= 1) {
        int t = (threadIdx.x >= ofs) ? sd[threadIdx.x - ofs] : 0;
        __syncthreads();
        sd[threadIdx.x] += t;
        __syncthreads();
    }
    if (i < NN) g_off[i] = sd[threadIdx.x] - v;           // exclusive within block
    if (threadIdx.x == SCAN_B - 1) g_bsum[blockIdx.x] = sd[threadIdx.x];
}

// cross-block scan + apply + sentinel + deg self-reset
__global__ void s3_apply() {
    __shared__ int sbase;
    int b = blockIdx.x;
    if (threadIdx.x < 32) {
        int p = 0;
        for (int i = threadIdx.x; i < b; i += 32) p += g_bsum[i];
#pragma unroll
        for (int o = 16; o; o >>= 1) p += __shfl_xor_sync(0xFFFFFFFFu, p, o);
        if (threadIdx.x == 0) sbase = p;
    }
    __syncthreads();
    int i = b * SCAN_B + threadIdx.x;
    if (i < NN) {
        int o = g_off[i] + sbase;
        g_off[i] = o;
        g_pos[i] = o;
        if (i == NN - 1) g_off[NN] = o + g_deg[i];   // sentinel
        g_deg[i] = 0;                                 // ready for next replay
    }
}

__global__ void k_scatter(const int* __restrict__ src, const int* __restrict__ dst) {
    int e = blockIdx.x * blockDim.x + threadIdx.x;
    if (e >= EE) return;
    int d = dst[e];
    int p = atomicAdd(&g_pos[d], 1);
    g_csr[p] = src[e];
}

// ---------------- K1: h1 = x @ W1 (+ attention logits) ----------------
__global__ void __launch_bounds__(256) k1_gemm1(
    const float* __restrict__ x, const float* __restrict__ W1,
    const float* __restrict__ a1s, const float* __restrict__ a1d)
{
    __shared__ float sW[128 * 64];
    __shared__ float sA[128];
    for (int i = threadIdx.x; i < 128 * 64; i += blockDim.x) sW[i] = W1[i];
    for (int i = threadIdx.x; i < 128; i += blockDim.x)
        sA[i] = (i < 64) ? a1s[i] : a1d[i - 64];
    __syncthreads();

    int row = blockIdx.x * blockDim.x + threadIdx.x;
    if (row >= NN) return;

    float acc[64];
#pragma unroll
    for (int j = 0; j < 64; j++) acc[j] = 0.0f;

    const float4* x4 = (const float4*)(x + (size_t)row * 128);
#pragma unroll 1
    for (int kc = 0; kc < 32; kc++) {
        float4 xv = __ldg(x4 + kc);
#pragma unroll
        for (int t = 0; t < 4; t++) {
            float xs = (t == 0) ? xv.x : (t == 1) ? xv.y : (t == 2) ? xv.z : xv.w;
            const float4* wrow = (const float4*)(sW + (kc * 4 + t) * 64);
#pragma unroll
            for (int j4 = 0; j4 < 16; j4++) {
                float4 w = wrow[j4];
                acc[j4 * 4 + 0] += xs * w.x;
                acc[j4 * 4 + 1] += xs * w.y;
                acc[j4 * 4 + 2] += xs * w.z;
                acc[j4 * 4 + 3] += xs * w.w;
            }
        }
    }

    float4* h1o = (float4*)(g_h1 + (size_t)row * 64);
#pragma unroll
    for (int j4 = 0; j4 < 16; j4++)
        h1o[j4] = make_float4(acc[j4 * 4], acc[j4 * 4 + 1], acc[j4 * 4 + 2], acc[j4 * 4 + 3]);

#pragma unroll
    for (int h = 0; h < 8; h++) {
        float s = 0.0f, d = 0.0f;
#pragma unroll
        for (int q = 0; q < 8; q++) {
            s += acc[h * 8 + q] * sA[h * 8 + q];
            d += acc[h * 8 + q] * sA[64 + h * 8 + q];
        }
        g_as1[row * 8 + h] = s;
        g_ad1[row * 8 + h] = d;
    }
}

// ---------------- G1K5: fused gather + softmax + ELU + GEMM2 + logits2 ----------------
__global__ void __launch_bounds__(256) g1k5(
    const float* __restrict__ b1, const float* __restrict__ W2,
    const float* __restrict__ a2s, const float* __restrict__ a2d)
{
    __shared__ float sW2[64 * 16];
    __shared__ float sb1[64];
    __shared__ float sa2[32];
    for (int i = threadIdx.x; i < 64 * 16; i += blockDim.x) sW2[i] = W2[i];
    if (threadIdx.x < 64) sb1[threadIdx.x] = b1[threadIdx.x];
    if (threadIdx.x < 32)
        sa2[threadIdx.x] = (threadIdx.x < 16) ? a2s[threadIdx.x] : a2d[threadIdx.x - 16];
    __syncthreads();

    int warp = (blockIdx.x * 256 + threadIdx.x) >> 5;
    int lane = threadIdx.x & 31;
    if (warp >= NN) return;
    int n = warp;
    int off = g_off[n];
    int deg = g_off[n + 1] - off;
    int h8 = lane & 7;            // head index in logit phase (lane = edge*8 + h8)
    int h4 = lane >> 2;           // head owning this lane's 2 dims
    float adf = g_ad1[n * 8 + h8];

    float2 acc = make_float2(0.0f, 0.0f);
    float den = 0.0f;

    for (int base = 0; base < deg; base += 32) {
        int idx = base + lane;
        int sreg = (idx < deg) ? g_csr[off + idx] : 0;
        int cnt = min(32, deg - base);
        for (int g = 0; g < cnt; g += 4) {
            int le = g + (lane >> 3);
            int sl = __shfl_sync(0xFFFFFFFFu, sreg, le);
            float e = g_as1[sl * 8 + h8] + adf;
            e = (e >= 0.0f) ? e : NEG_SLOPE * e;
            float p = __expf(e);
            if (base + le >= deg) p = 0.0f;
#pragma unroll
            for (int j = 0; j < 4; j++) {
                int s = __shfl_sync(0xFFFFFFFFu, sreg, g + j);
                float pj = __shfl_sync(0xFFFFFFFFu, p, j * 8 + h4);
                float2 v = *(const float2*)(g_h1 + (size_t)s * 64 + 2 * lane);
                acc.x += pj * v.x;
                acc.y += pj * v.y;
                den += pj;
            }
        }
    }

    float inv = (den > 0.0f) ? (1.0f / den) : 0.0f;
    float r0 = acc.x * inv + sb1[2 * lane];
    float r1 = acc.y * inv + sb1[2 * lane + 1];
    r0 = (r0 > 0.0f) ? r0 : (__expf(r0) - 1.0f);
    r1 = (r1 > 0.0f) ? r1 : (__expf(r1) - 1.0f);

    // ---- fused GEMM2: g2[c] = sum_k feat[k] * W2[k][c], via shuffle broadcast ----
    float a2 = 0.0f;
#pragma unroll
    for (int l = 0; l < 32; l++) {
        float f0 = __shfl_sync(0xFFFFFFFFu, r0, l);
        float f1 = __shfl_sync(0xFFFFFFFFu, r1, l);
        if (lane < 16)
            a2 += f0 * sW2[(2 * l) * 16 + lane] + f1 * sW2[(2 * l + 1) * 16 + lane];
    }

    // layer2 attention logits: dot(g2_16, a2s) and dot(g2_16, a2d)
    float ts = (lane < 16) ? a2 * sa2[lane] : 0.0f;
    float td = (lane < 16) ? a2 * sa2[16 + lane] : 0.0f;
#pragma unroll
    for (int o = 8; o; o >>= 1) {
        ts += __shfl_xor_sync(0xFFFFFFFFu, ts, o);
        td += __shfl_xor_sync(0xFFFFFFFFu, td, o);
    }
    if (lane == 0) {
        g_as2[n] = ts;
        g_ad2[n] = td;
    }
    if (lane < 16) g_g2[(size_t)n * 16 + lane] = a2;
}

// ---------------- G2: warp-per-dst gather, 32-edge batched logits ----------------
__global__ void __launch_bounds__(256) g2_gather(const float* __restrict__ b2,
                                                 float* __restrict__ out) {
    int warp = (blockIdx.x * 256 + threadIdx.x) >> 5;
    int lane = threadIdx.x & 31;
    if (warp >= NN) return;
    int n = warp;
    int off = g_off[n];
    int deg = g_off[n + 1] - off;
    int half = lane >> 4;      // which of 2 edges per accumulation step
    int d16 = lane & 15;       // output class
    float ad = g_ad2[n];

    float acc = 0.0f, den = 0.0f;

    for (int base = 0; base < deg; base += 32) {
        int idx = base + lane;
        int sreg = (idx < deg) ? g_csr[off + idx] : 0;
        float e = g_as2[sreg] + ad;
        e = (e >= 0.0f) ? e : NEG_SLOPE * e;
        float p = __expf(e);
        if (idx >= deg) p = 0.0f;
        int cnt = min(32, deg - base);
        for (int g = 0; g < cnt; g += 2) {
            int s = __shfl_sync(0xFFFFFFFFu, sreg, g + half);
            float pj = __shfl_sync(0xFFFFFFFFu, p, g + half);
            float v = g_g2[(size_t)s * 16 + d16];
            acc += pj * v;
            den += pj;
        }
    }

    acc += __shfl_xor_sync(0xFFFFFFFFu, acc, 16);
    den += __shfl_xor_sync(0xFFFFFFFFu, den, 16);

    float z = ((den > 0.0f) ? (acc / den) : 0.0f) + b2[d16];

    float m = z;
#pragma unroll
    for (int ofs = 1; ofs < 16; ofs <<= 1)
        m = fmaxf(m, __shfl_xor_sync(0xFFFFFFFFu, m, ofs));
    float sum = __expf(z - m);
#pragma unroll
    for (int ofs = 1; ofs < 16; ofs <<= 1)
        sum += __shfl_xor_sync(0xFFFFFFFFu, sum, ofs);
    float lse = m + logf(sum);

    if (lane < 16) out[(size_t)n * 16 + d16] = z - lse;
}

// ---------------- launcher ----------------
extern "C" void kernel_launch(void* const* d_in, const int* in_sizes, int n_in,
                              void* d_out, int out_size) {
    const float* x   = (const float*)d_in[0];
    const int*   ei  = (const int*)d_in[1];
    const float* W1  = (const float*)d_in[2];
    const float* a1s = (const float*)d_in[3];
    const float* a1d = (const float*)d_in[4];
    const float* b1  = (const float*)d_in[5];
    const float* W2  = (const float*)d_in[6];
    const float* a2s = (const float*)d_in[7];
    const float* a2d = (const float*)d_in[8];
    const float* b2  = (const float*)d_in[9];
    float* out = (float*)d_out;

    const int* src = ei;
    const int* dst = ei + EE;

    const int TB = 256;
    // CSR build (g_deg arrives zeroed: static init on first call, s3 reset after)
    k_hist<<<(EE + TB - 1) / TB, TB>>>(dst);
    s1_scan<<<NBLK, SCAN_B>>>();
    s3_apply<<<NBLK, SCAN_B>>>();
    k_scatter<<<(EE + TB - 1) / TB, TB>>>(src, dst);
    // layer 1 + fused layer2 GEMM
    k1_gemm1<<<(NN + TB - 1) / TB, TB>>>(x, W1, a1s, a1d);
    g1k5<<<(NN * 32 + TB - 1) / TB, TB>>>(b1, W2, a2s, a2d);
    // layer 2 aggregation + log-softmax
    g2_gather<<<(NN * 32 + TB - 1) / TB, TB>>>(b2, out);
}

// round 8
// speedup vs baseline: 1.0881x; 1.0881x over previous
#include <cuda_runtime.h>
#include <cuda_bf16.h>
#include <math.h>

#define NN 100000
#define EE 1600000
#define NEG_SLOPE 0.2f
#define SCAN_B 512
#define NBLK ((NN + SCAN_B - 1) / SCAN_B)   // 196

// ---------------- scratch (device globals) ----------------
__device__ float g_h1[NN * 64];     // layer1 GEMM output [N,H*D]
__device__ float g_as1[NN * 8];
__device__ float g_ad1[NN * 8];
__device__ float g_out1[NN * 64];   // layer1 final (ELU'd)
__device__ float g_g2[NN * 16];     // layer2 GEMM output
__device__ float g_as2[NN];
__device__ float g_ad2[NN];
__device__ int   g_deg[NN];         // zero at load; self-reset by s3 each call
__device__ int   g_off[NN + 1];     // CSR offsets, sentinel off[NN]=EE
__device__ int   g_pos[NN];
__device__ int   g_csr[EE];         // src node ids, grouped by dst
__device__ int   g_bsum[NBLK];

// ---------------- CSR build: 4 edges/thread for atomic-latency overlap ----------------
__global__ void k_hist(const int* __restrict__ dst) {
    int t = blockIdx.x * blockDim.x + threadIdx.x;   // over EE/4
    if (t >= EE / 4) return;
    int4 d4 = ((const int4*)dst)[t];
    atomicAdd(&g_deg[d4.x], 1);
    atomicAdd(&g_deg[d4.y], 1);
    atomicAdd(&g_deg[d4.z], 1);
    atomicAdd(&g_deg[d4.w], 1);
}

__global__ void s1_scan() {
    __shared__ int sd[SCAN_B];
    int i = blockIdx.x * SCAN_B + threadIdx.x;
    int v = (i < NN) ? g_deg[i] : 0;
    sd[threadIdx.x] = v;
    __syncthreads();
    for (int ofs = 1; ofs < SCAN_B; ofs <<= 1) {
        int t = (threadIdx.x >= ofs) ? sd[threadIdx.x - ofs] : 0;
        __syncthreads();
        sd[threadIdx.x] += t;
        __syncthreads();
    }
    if (i < NN) g_off[i] = sd[threadIdx.x] - v;           // exclusive within block
    if (threadIdx.x == SCAN_B - 1) g_bsum[blockIdx.x] = sd[threadIdx.x];
}

// cross-block scan + apply + sentinel + deg self-reset
__global__ void s3_apply() {
    __shared__ int sbase;
    int b = blockIdx.x;
    if (threadIdx.x < 32) {
        int p = 0;
        for (int i = threadIdx.x; i < b; i += 32) p += g_bsum[i];
#pragma unroll
        for (int o = 16; o; o >>= 1) p += __shfl_xor_sync(0xFFFFFFFFu, p, o);
        if (threadIdx.x == 0) sbase = p;
    }
    __syncthreads();
    int i = b * SCAN_B + threadIdx.x;
    if (i < NN) {
        int o = g_off[i] + sbase;
        g_off[i] = o;
        g_pos[i] = o;
        if (i == NN - 1) g_off[NN] = o + g_deg[i];   // sentinel
        g_deg[i] = 0;                                 // ready for next replay
    }
}

__global__ void k_scatter(const int* __restrict__ src, const int* __restrict__ dst) {
    int t = blockIdx.x * blockDim.x + threadIdx.x;   // over EE/4
    if (t >= EE / 4) return;
    int4 s4 = ((const int4*)src)[t];
    int4 d4 = ((const int4*)dst)[t];
    int p0 = atomicAdd(&g_pos[d4.x], 1);
    int p1 = atomicAdd(&g_pos[d4.y], 1);
    int p2 = atomicAdd(&g_pos[d4.z], 1);
    int p3 = atomicAdd(&g_pos[d4.w], 1);
    g_csr[p0] = s4.x;
    g_csr[p1] = s4.y;
    g_csr[p2] = s4.z;
    g_csr[p3] = s4.w;
}

// ---------------- K1: h1 = x @ W1 (+ attention logits) ----------------
__global__ void __launch_bounds__(256) k1_gemm1(
    const float* __restrict__ x, const float* __restrict__ W1,
    const float* __restrict__ a1s, const float* __restrict__ a1d)
{
    __shared__ float sW[128 * 64];
    __shared__ float sA[128];
    for (int i = threadIdx.x; i < 128 * 64; i += blockDim.x) sW[i] = W1[i];
    for (int i = threadIdx.x; i < 128; i += blockDim.x)
        sA[i] = (i < 64) ? a1s[i] : a1d[i - 64];
    __syncthreads();

    int row = blockIdx.x * blockDim.x + threadIdx.x;
    if (row >= NN) return;

    float acc[64];
#pragma unroll
    for (int j = 0; j < 64; j++) acc[j] = 0.0f;

    const float4* x4 = (const float4*)(x + (size_t)row * 128);
#pragma unroll 1
    for (int kc = 0; kc < 32; kc++) {
        float4 xv = __ldg(x4 + kc);
#pragma unroll
        for (int t = 0; t < 4; t++) {
            float xs = (t == 0) ? xv.x : (t == 1) ? xv.y : (t == 2) ? xv.z : xv.w;
            const float4* wrow = (const float4*)(sW + (kc * 4 + t) * 64);
#pragma unroll
            for (int j4 = 0; j4 < 16; j4++) {
                float4 w = wrow[j4];
                acc[j4 * 4 + 0] += xs * w.x;
                acc[j4 * 4 + 1] += xs * w.y;
                acc[j4 * 4 + 2] += xs * w.z;
                acc[j4 * 4 + 3] += xs * w.w;
            }
        }
    }

    float4* h1o = (float4*)(g_h1 + (size_t)row * 64);
#pragma unroll
    for (int j4 = 0; j4 < 16; j4++)
        h1o[j4] = make_float4(acc[j4 * 4], acc[j4 * 4 + 1], acc[j4 * 4 + 2], acc[j4 * 4 + 3]);

#pragma unroll
    for (int h = 0; h < 8; h++) {
        float s = 0.0f, d = 0.0f;
#pragma unroll
        for (int q = 0; q < 8; q++) {
            s += acc[h * 8 + q] * sA[h * 8 + q];
            d += acc[h * 8 + q] * sA[64 + h * 8 + q];
        }
        g_as1[row * 8 + h] = s;
        g_ad1[row * 8 + h] = d;
    }
}

// ---------------- G1: warp-per-dst gather, 4-edge batched logits ----------------
__global__ void __launch_bounds__(256) g1_gather(const float* __restrict__ b1) {
    int warp = (blockIdx.x * 256 + threadIdx.x) >> 5;
    int lane = threadIdx.x & 31;
    if (warp >= NN) return;
    int n = warp;
    int off = g_off[n];
    int deg = g_off[n + 1] - off;
    int h8 = lane & 7;            // head index in logit phase (lane = edge*8 + h8)
    int h4 = lane >> 2;           // head owning this lane's 2 dims
    float adf = g_ad1[n * 8 + h8];

    float2 acc = make_float2(0.0f, 0.0f);
    float den = 0.0f;

    for (int base = 0; base < deg; base += 32) {
        int idx = base + lane;
        int sreg = (idx < deg) ? g_csr[off + idx] : 0;
        int cnt = min(32, deg - base);
        for (int g = 0; g < cnt; g += 4) {
            int le = g + (lane >> 3);
            int sl = __shfl_sync(0xFFFFFFFFu, sreg, le);
            float e = g_as1[sl * 8 + h8] + adf;
            e = (e >= 0.0f) ? e : NEG_SLOPE * e;
            float p = __expf(e);
            if (base + le >= deg) p = 0.0f;
#pragma unroll
            for (int j = 0; j < 4; j++) {
                int s = __shfl_sync(0xFFFFFFFFu, sreg, g + j);
                float pj = __shfl_sync(0xFFFFFFFFu, p, j * 8 + h4);
                float2 v = *(const float2*)(g_h1 + (size_t)s * 64 + 2 * lane);
                acc.x += pj * v.x;
                acc.y += pj * v.y;
                den += pj;
            }
        }
    }

    float inv = (den > 0.0f) ? (1.0f / den) : 0.0f;
    float r0 = acc.x * inv + b1[2 * lane];
    float r1 = acc.y * inv + b1[2 * lane + 1];
    r0 = (r0 > 0.0f) ? r0 : (__expf(r0) - 1.0f);
    r1 = (r1 > 0.0f) ? r1 : (__expf(r1) - 1.0f);
    *(float2*)(g_out1 + (size_t)n * 64 + 2 * lane) = make_float2(r0, r1);
}

// ---------------- K5: g2 = elu_h @ W2 (+ layer2 attention logits) ----------------
__global__ void __launch_bounds__(256) k5_gemm2(
    const float* __restrict__ W2, const float* __restrict__ a2s,
    const float* __restrict__ a2d)
{
    __shared__ float sW[64 * 16];
    __shared__ float sA[32];
    for (int i = threadIdx.x; i < 64 * 16; i += blockDim.x) sW[i] = W2[i];
    for (int i = threadIdx.x; i < 32; i += blockDim.x)
        sA[i] = (i < 16) ? a2s[i] : a2d[i - 16];
    __syncthreads();

    int row = blockIdx.x * blockDim.x + threadIdx.x;
    if (row >= NN) return;

    float acc[16];
#pragma unroll
    for (int j = 0; j < 16; j++) acc[j] = 0.0f;

    const float4* x4 = (const float4*)(g_out1 + (size_t)row * 64);
#pragma unroll 1
    for (int kc = 0; kc < 16; kc++) {
        float4 xv = x4[kc];
#pragma unroll
        for (int t = 0; t < 4; t++) {
            float xs = (t == 0) ? xv.x : (t == 1) ? xv.y : (t == 2) ? xv.z : xv.w;
            const float4* wrow = (const float4*)(sW + (kc * 4 + t) * 16);
#pragma unroll
            for (int j4 = 0; j4 < 4; j4++) {
                float4 w = wrow[j4];
                acc[j4 * 4 + 0] += xs * w.x;
                acc[j4 * 4 + 1] += xs * w.y;
                acc[j4 * 4 + 2] += xs * w.z;
                acc[j4 * 4 + 3] += xs * w.w;
            }
        }
    }

    float4* go = (float4*)(g_g2 + (size_t)row * 16);
#pragma unroll
    for (int j4 = 0; j4 < 4; j4++)
        go[j4] = make_float4(acc[j4 * 4], acc[j4 * 4 + 1], acc[j4 * 4 + 2], acc[j4 * 4 + 3]);

    float s = 0.0f, d = 0.0f;
#pragma unroll
    for (int j = 0; j < 16; j++) { s += acc[j] * sA[j]; d += acc[j] * sA[16 + j]; }
    g_as2[row] = s;
    g_ad2[row] = d;
}

// ---------------- G2: warp-per-dst gather, 32-edge batched logits ----------------
__global__ void __launch_bounds__(256) g2_gather(const float* __restrict__ b2,
                                                 float* __restrict__ out) {
    int warp = (blockIdx.x * 256 + threadIdx.x) >> 5;
    int lane = threadIdx.x & 31;
    if (warp >= NN) return;
    int n = warp;
    int off = g_off[n];
    int deg = g_off[n + 1] - off;
    int half = lane >> 4;      // which of 2 edges per accumulation step
    int d16 = lane & 15;       // output class
    float ad = g_ad2[n];

    float acc = 0.0f, den = 0.0f;

    for (int base = 0; base < deg; base += 32) {
        int idx = base + lane;
        int sreg = (idx < deg) ? g_csr[off + idx] : 0;
        float e = g_as2[sreg] + ad;
        e = (e >= 0.0f) ? e : NEG_SLOPE * e;
        float p = __expf(e);
        if (idx >= deg) p = 0.0f;
        int cnt = min(32, deg - base);
        for (int g = 0; g < cnt; g += 2) {
            int s = __shfl_sync(0xFFFFFFFFu, sreg, g + half);
            float pj = __shfl_sync(0xFFFFFFFFu, p, g + half);
            float v = g_g2[(size_t)s * 16 + d16];
            acc += pj * v;
            den += pj;
        }
    }

    acc += __shfl_xor_sync(0xFFFFFFFFu, acc, 16);
    den += __shfl_xor_sync(0xFFFFFFFFu, den, 16);

    float z = ((den > 0.0f) ? (acc / den) : 0.0f) + b2[d16];

    float m = z;
#pragma unroll
    for (int ofs = 1; ofs < 16; ofs <<= 1)
        m = fmaxf(m, __shfl_xor_sync(0xFFFFFFFFu, m, ofs));
    float sum = __expf(z - m);
#pragma unroll
    for (int ofs = 1; ofs < 16; ofs <<= 1)
        sum += __shfl_xor_sync(0xFFFFFFFFu, sum, ofs);
    float lse = m + logf(sum);

    if (lane < 16) out[(size_t)n * 16 + d16] = z - lse;
}

// ---------------- launcher ----------------
extern "C" void kernel_launch(void* const* d_in, const int* in_sizes, int n_in,
                              void* d_out, int out_size) {
    const float* x   = (const float*)d_in[0];
    const int*   ei  = (const int*)d_in[1];
    const float* W1  = (const float*)d_in[2];
    const float* a1s = (const float*)d_in[3];
    const float* a1d = (const float*)d_in[4];
    const float* b1  = (const float*)d_in[5];
    const float* W2  = (const float*)d_in[6];
    const float* a2s = (const float*)d_in[7];
    const float* a2d = (const float*)d_in[8];
    const float* b2  = (const float*)d_in[9];
    float* out = (float*)d_out;

    const int* src = ei;
    const int* dst = ei + EE;

    const int TB = 256;
    // CSR build (g_deg arrives zeroed: static init on first call, s3 reset after)
    k_hist<<<(EE / 4 + TB - 1) / TB, TB>>>(dst);
    s1_scan<<<NBLK, SCAN_B>>>();
    s3_apply<<<NBLK, SCAN_B>>>();
    k_scatter<<<(EE / 4 + TB - 1) / TB, TB>>>(src, dst);
    // layer 1
    k1_gemm1<<<(NN + TB - 1) / TB, TB>>>(x, W1, a1s, a1d);
    g1_gather<<<(NN * 32 + TB - 1) / TB, TB>>>(b1);
    // layer 2
    k5_gemm2<<<(NN + TB - 1) / TB, TB>>>(W2, a2s, a2d);
    g2_gather<<<(NN * 32 + TB - 1) / TB, TB>>>(b2, out);
}

// round 9
// speedup vs baseline: 1.1727x; 1.0778x over previous
#include <cuda_runtime.h>
#include <cuda_bf16.h>
#include <math.h>

#define NN 100000
#define EE 1600000
#define NEG_SLOPE 0.2f
#define SCAN_B 512
#define NBLK ((NN + SCAN_B - 1) / SCAN_B)   // 196
#define GEMM_BLOCKS ((NN + 255) / 256)       // 391
#define HIST_BLOCKS ((EE / 4 + 255) / 256)   // 1563

// ---------------- scratch (device globals) ----------------
__device__ float g_h1[NN * 64];     // layer1 GEMM output [N,H*D]
__device__ float g_as1[NN * 8];
__device__ float g_ad1[NN * 8];
__device__ float g_out1[NN * 64];   // layer1 final (ELU'd)
__device__ float g_g2[NN * 16];     // layer2 GEMM output
__device__ float g_as2[NN];
__device__ float g_ad2[NN];
__device__ int   g_deg[NN];         // zero at load; self-reset by s3 each call
__device__ int   g_off[NN + 1];     // CSR offsets, sentinel off[NN]=EE
__device__ int   g_rank[EE];        // per-edge rank within its dst segment
__device__ int   g_csr[EE];         // src node ids, grouped by dst
__device__ int   g_bsum[NBLK];

// ---------------- KA: fused GEMM1 (+logits) and degree histogram (+ranks) ----------------
__global__ void __launch_bounds__(256) kA_gemm1_hist(
    const float* __restrict__ x, const float* __restrict__ W1,
    const float* __restrict__ a1s, const float* __restrict__ a1d,
    const int* __restrict__ dst)
{
    if (blockIdx.x >= GEMM_BLOCKS) {
        // ---- histogram part: 4 edges/thread, record ranks ----
        int t = (blockIdx.x - GEMM_BLOCKS) * 256 + threadIdx.x;
        if (t >= EE / 4) return;
        int4 d4 = ((const int4*)dst)[t];
        int r0 = atomicAdd(&g_deg[d4.x], 1);
        int r1 = atomicAdd(&g_deg[d4.y], 1);
        int r2 = atomicAdd(&g_deg[d4.z], 1);
        int r3 = atomicAdd(&g_deg[d4.w], 1);
        ((int4*)g_rank)[t] = make_int4(r0, r1, r2, r3);
        return;
    }

    // ---- GEMM part ----
    __shared__ float sW[128 * 64];
    __shared__ float sA[128];
    for (int i = threadIdx.x; i < 128 * 64; i += blockDim.x) sW[i] = W1[i];
    for (int i = threadIdx.x; i < 128; i += blockDim.x)
        sA[i] = (i < 64) ? a1s[i] : a1d[i - 64];
    __syncthreads();

    int row = blockIdx.x * blockDim.x + threadIdx.x;
    if (row >= NN) return;

    float acc[64];
#pragma unroll
    for (int j = 0; j < 64; j++) acc[j] = 0.0f;

    const float4* x4 = (const float4*)(x + (size_t)row * 128);
#pragma unroll 1
    for (int kc = 0; kc < 32; kc++) {
        float4 xv = __ldg(x4 + kc);
#pragma unroll
        for (int t = 0; t < 4; t++) {
            float xs = (t == 0) ? xv.x : (t == 1) ? xv.y : (t == 2) ? xv.z : xv.w;
            const float4* wrow = (const float4*)(sW + (kc * 4 + t) * 64);
#pragma unroll
            for (int j4 = 0; j4 < 16; j4++) {
                float4 w = wrow[j4];
                acc[j4 * 4 + 0] += xs * w.x;
                acc[j4 * 4 + 1] += xs * w.y;
                acc[j4 * 4 + 2] += xs * w.z;
                acc[j4 * 4 + 3] += xs * w.w;
            }
        }
    }

    float4* h1o = (float4*)(g_h1 + (size_t)row * 64);
#pragma unroll
    for (int j4 = 0; j4 < 16; j4++)
        h1o[j4] = make_float4(acc[j4 * 4], acc[j4 * 4 + 1], acc[j4 * 4 + 2], acc[j4 * 4 + 3]);

#pragma unroll
    for (int h = 0; h < 8; h++) {
        float s = 0.0f, d = 0.0f;
#pragma unroll
        for (int q = 0; q < 8; q++) {
            s += acc[h * 8 + q] * sA[h * 8 + q];
            d += acc[h * 8 + q] * sA[64 + h * 8 + q];
        }
        g_as1[row * 8 + h] = s;
        g_ad1[row * 8 + h] = d;
    }
}

// ---------------- scans ----------------
__global__ void s1_scan() {
    __shared__ int sd[SCAN_B];
    int i = blockIdx.x * SCAN_B + threadIdx.x;
    int v = (i < NN) ? g_deg[i] : 0;
    sd[threadIdx.x] = v;
    __syncthreads();
    for (int ofs = 1; ofs < SCAN_B; ofs <<= 1) {
        int t = (threadIdx.x >= ofs) ? sd[threadIdx.x - ofs] : 0;
        __syncthreads();
        sd[threadIdx.x] += t;
        __syncthreads();
    }
    if (i < NN) g_off[i] = sd[threadIdx.x] - v;           // exclusive within block
    if (threadIdx.x == SCAN_B - 1) g_bsum[blockIdx.x] = sd[threadIdx.x];
}

// cross-block scan + apply + sentinel + deg self-reset
__global__ void s3_apply() {
    __shared__ int sbase;
    int b = blockIdx.x;
    if (threadIdx.x < 32) {
        int p = 0;
        for (int i = threadIdx.x; i < b; i += 32) p += g_bsum[i];
#pragma unroll
        for (int o = 16; o; o >>= 1) p += __shfl_xor_sync(0xFFFFFFFFu, p, o);
        if (threadIdx.x == 0) sbase = p;
    }
    __syncthreads();
    int i = b * SCAN_B + threadIdx.x;
    if (i < NN) {
        int o = g_off[i] + sbase;
        g_off[i] = o;
        if (i == NN - 1) g_off[NN] = o + g_deg[i];   // sentinel
        g_deg[i] = 0;                                 // ready for next replay
    }
}

// ---------------- scatter: atomic-free (uses precomputed ranks) ----------------
__global__ void k_scatter(const int* __restrict__ src, const int* __restrict__ dst) {
    int t = blockIdx.x * blockDim.x + threadIdx.x;   // over EE/4
    if (t >= EE / 4) return;
    int4 s4 = ((const int4*)src)[t];
    int4 d4 = ((const int4*)dst)[t];
    int4 r4 = ((const int4*)g_rank)[t];
    g_csr[g_off[d4.x] + r4.x] = s4.x;
    g_csr[g_off[d4.y] + r4.y] = s4.y;
    g_csr[g_off[d4.z] + r4.z] = s4.z;
    g_csr[g_off[d4.w] + r4.w] = s4.w;
}

// ---------------- G1: warp-per-dst gather, 4-edge batched logits ----------------
__global__ void __launch_bounds__(256) g1_gather(const float* __restrict__ b1) {
    int warp = (blockIdx.x * 256 + threadIdx.x) >> 5;
    int lane = threadIdx.x & 31;
    if (warp >= NN) return;
    int n = warp;
    int off = g_off[n];
    int deg = g_off[n + 1] - off;
    int h8 = lane & 7;            // head index in logit phase (lane = edge*8 + h8)
    int h4 = lane >> 2;           // head owning this lane's 2 dims
    float adf = g_ad1[n * 8 + h8];

    float2 acc = make_float2(0.0f, 0.0f);
    float den = 0.0f;

    for (int base = 0; base < deg; base += 32) {
        int idx = base + lane;
        int sreg = (idx < deg) ? g_csr[off + idx] : 0;
        int cnt = min(32, deg - base);
        for (int g = 0; g < cnt; g += 4) {
            int le = g + (lane >> 3);
            int sl = __shfl_sync(0xFFFFFFFFu, sreg, le);
            float e = g_as1[sl * 8 + h8] + adf;
            e = (e >= 0.0f) ? e : NEG_SLOPE * e;
            float p = __expf(e);
            if (base + le >= deg) p = 0.0f;
#pragma unroll
            for (int j = 0; j < 4; j++) {
                int s = __shfl_sync(0xFFFFFFFFu, sreg, g + j);
                float pj = __shfl_sync(0xFFFFFFFFu, p, j * 8 + h4);
                float2 v = *(const float2*)(g_h1 + (size_t)s * 64 + 2 * lane);
                acc.x += pj * v.x;
                acc.y += pj * v.y;
                den += pj;
            }
        }
    }

    float inv = (den > 0.0f) ? (1.0f / den) : 0.0f;
    float r0 = acc.x * inv + b1[2 * lane];
    float r1 = acc.y * inv + b1[2 * lane + 1];
    r0 = (r0 > 0.0f) ? r0 : (__expf(r0) - 1.0f);
    r1 = (r1 > 0.0f) ? r1 : (__expf(r1) - 1.0f);
    *(float2*)(g_out1 + (size_t)n * 64 + 2 * lane) = make_float2(r0, r1);
}

// ---------------- K5: g2 = elu_h @ W2 (+ layer2 attention logits) ----------------
__global__ void __launch_bounds__(256) k5_gemm2(
    const float* __restrict__ W2, const float* __restrict__ a2s,
    const float* __restrict__ a2d)
{
    __shared__ float sW[64 * 16];
    __shared__ float sA[32];
    for (int i = threadIdx.x; i < 64 * 16; i += blockDim.x) sW[i] = W2[i];
    for (int i = threadIdx.x; i < 32; i += blockDim.x)
        sA[i] = (i < 16) ? a2s[i] : a2d[i - 16];
    __syncthreads();

    int row = blockIdx.x * blockDim.x + threadIdx.x;
    if (row >= NN) return;

    float acc[16];
#pragma unroll
    for (int j = 0; j < 16; j++) acc[j] = 0.0f;

    const float4* x4 = (const float4*)(g_out1 + (size_t)row * 64);
#pragma unroll 1
    for (int kc = 0; kc < 16; kc++) {
        float4 xv = x4[kc];
#pragma unroll
        for (int t = 0; t < 4; t++) {
            float xs = (t == 0) ? xv.x : (t == 1) ? xv.y : (t == 2) ? xv.z : xv.w;
            const float4* wrow = (const float4*)(sW + (kc * 4 + t) * 16);
#pragma unroll
            for (int j4 = 0; j4 < 4; j4++) {
                float4 w = wrow[j4];
                acc[j4 * 4 + 0] += xs * w.x;
                acc[j4 * 4 + 1] += xs * w.y;
                acc[j4 * 4 + 2] += xs * w.z;
                acc[j4 * 4 + 3] += xs * w.w;
            }
        }
    }

    float4* go = (float4*)(g_g2 + (size_t)row * 16);
#pragma unroll
    for (int j4 = 0; j4 < 4; j4++)
        go[j4] = make_float4(acc[j4 * 4], acc[j4 * 4 + 1], acc[j4 * 4 + 2], acc[j4 * 4 + 3]);

    float s = 0.0f, d = 0.0f;
#pragma unroll
    for (int j = 0; j < 16; j++) { s += acc[j] * sA[j]; d += acc[j] * sA[16 + j]; }
    g_as2[row] = s;
    g_ad2[row] = d;
}

// ---------------- G2: warp-per-dst gather, 32-edge batched logits ----------------
__global__ void __launch_bounds__(256) g2_gather(const float* __restrict__ b2,
                                                 float* __restrict__ out) {
    int warp = (blockIdx.x * 256 + threadIdx.x) >> 5;
    int lane = threadIdx.x & 31;
    if (warp >= NN) return;
    int n = warp;
    int off = g_off[n];
    int deg = g_off[n + 1] - off;
    int half = lane >> 4;      // which of 2 edges per accumulation step
    int d16 = lane & 15;       // output class
    float ad = g_ad2[n];

    float acc = 0.0f, den = 0.0f;

    for (int base = 0; base < deg; base += 32) {
        int idx = base + lane;
        int sreg = (idx < deg) ? g_csr[off + idx] : 0;
        float e = g_as2[sreg] + ad;
        e = (e >= 0.0f) ? e : NEG_SLOPE * e;
        float p = __expf(e);
        if (idx >= deg) p = 0.0f;
        int cnt = min(32, deg - base);
        for (int g = 0; g < cnt; g += 2) {
            int s = __shfl_sync(0xFFFFFFFFu, sreg, g + half);
            float pj = __shfl_sync(0xFFFFFFFFu, p, g + half);
            float v = g_g2[(size_t)s * 16 + d16];
            acc += pj * v;
            den += pj;
        }
    }

    acc += __shfl_xor_sync(0xFFFFFFFFu, acc, 16);
    den += __shfl_xor_sync(0xFFFFFFFFu, den, 16);

    float z = ((den > 0.0f) ? (acc / den) : 0.0f) + b2[d16];

    float m = z;
#pragma unroll
    for (int ofs = 1; ofs < 16; ofs <<= 1)
        m = fmaxf(m, __shfl_xor_sync(0xFFFFFFFFu, m, ofs));
    float sum = __expf(z - m);
#pragma unroll
    for (int ofs = 1; ofs < 16; ofs <<= 1)
        sum += __shfl_xor_sync(0xFFFFFFFFu, sum, ofs);
    float lse = m + logf(sum);

    if (lane < 16) out[(size_t)n * 16 + d16] = z - lse;
}

// ---------------- launcher ----------------
extern "C" void kernel_launch(void* const* d_in, const int* in_sizes, int n_in,
                              void* d_out, int out_size) {
    const float* x   = (const float*)d_in[0];
    const int*   ei  = (const int*)d_in[1];
    const float* W1  = (const float*)d_in[2];
    const float* a1s = (const float*)d_in[3];
    const float* a1d = (const float*)d_in[4];
    const float* b1  = (const float*)d_in[5];
    const float* W2  = (const float*)d_in[6];
    const float* a2s = (const float*)d_in[7];
    const float* a2d = (const float*)d_in[8];
    const float* b2  = (const float*)d_in[9];
    float* out = (float*)d_out;

    const int* src = ei;
    const int* dst = ei + EE;

    const int TB = 256;
    // fused GEMM1 + histogram (independent work, one launch)
    kA_gemm1_hist<<<GEMM_BLOCKS + HIST_BLOCKS, TB>>>(x, W1, a1s, a1d, dst);
    s1_scan<<<NBLK, SCAN_B>>>();
    s3_apply<<<NBLK, SCAN_B>>>();
    k_scatter<<<(EE / 4 + TB - 1) / TB, TB>>>(src, dst);   // atomic-free
    // layer 1 aggregation
    g1_gather<<<(NN * 32 + TB - 1) / TB, TB>>>(b1);
    // layer 2
    k5_gemm2<<<(NN + TB - 1) / TB, TB>>>(W2, a2s, a2d);
    g2_gather<<<(NN * 32 + TB - 1) / TB, TB>>>(b2, out);
}